// round 3
// baseline (speedup 1.0000x reference)
#include <cuda_runtime.h>
#include <cstdint>
#include <cstddef>

// ============================================================================
// GCN 2-layer: N=100000 nodes, E=1.6M edges (+self loops), 128 -> 128 -> 64.
//   deg[d] = 1 + #edges into d ; dinv = rsqrt(deg)
//   h1 = relu( scatter(x@W1) + b1 ) ; out = log_softmax( scatter(h1@W2) + b2 )
// where scatter(h)[d] = h[d]*dinv[d]^2 (self loop) + sum_e h[src_e]*dinv[s]*dinv[d]
// ============================================================================

#define NN 100000
#define D1 128
#define D2 64

// Scratch (allocation-free rule: __device__ globals)
__device__ float g_dinv[NN];                       // deg -> dinv (in place)
__device__ float g_h1[(size_t)NN * D1];            // x @ W1
__device__ float g_a1[(size_t)NN * D1];            // aggregated layer 1
__device__ float g_h2[(size_t)NN * D2];            // relu(a1+b1) @ W2
__device__ int   g_is64;                           // edge_index dtype flag

// ---------------------------------------------------------------------------
// Edge dtype detection: if edge_index is int64, every odd 32-bit word (high
// half of a nonnegative value < 2^31) is zero. For int32 random node ids in
// [0,1e5), 1024 consecutive odd words all zero is impossible (~1e-5120).
// ---------------------------------------------------------------------------
__global__ void detect_kernel(const int* __restrict__ e32) {
    int t = threadIdx.x;                       // 1024 threads, 1 block
    int nz = (e32[2 * t + 1] != 0) ? 1 : 0;
    int any = __syncthreads_or(nz);
    if (t == 0) g_is64 = (any == 0) ? 1 : 0;
}

__device__ __forceinline__ void load_edge(const void* __restrict__ ei, int e,
                                          int E, int& s, int& d) {
    if (g_is64) {
        const long long* p = (const long long*)ei;
        s = (int)p[e];
        d = (int)p[E + e];
    } else {
        const int* p = (const int*)ei;
        s = p[e];
        d = p[E + e];
    }
}

// ---------------------------------------------------------------------------
// Degree / normalization
// ---------------------------------------------------------------------------
__global__ void deg_init_kernel() {
    int i = blockIdx.x * blockDim.x + threadIdx.x;
    if (i < NN) g_dinv[i] = 1.0f;              // self loop contributes 1
}

__global__ void deg_scatter_kernel(const void* __restrict__ ei, int E) {
    int e = blockIdx.x * blockDim.x + threadIdx.x;
    if (e >= E) return;
    int s, d;
    load_edge(ei, e, E, s, d);
    atomicAdd(&g_dinv[d], 1.0f);               // return unused -> REDG
}

__global__ void deg_inv_kernel() {
    int i = blockIdx.x * blockDim.x + threadIdx.x;
    if (i < NN) g_dinv[i] = rsqrtf(g_dinv[i]); // deg >= 1 always
}

// ---------------------------------------------------------------------------
// Register-tiled SGEMM: C[M,N] = A[M,K] @ B[K,N]  (optionally A := relu(A+bias[k]))
// BM x BN block tile, BK k-chunk, TM x TN per thread, 256 threads.
// ---------------------------------------------------------------------------
template <int BM, int BN, int BK, int TM, int TN, bool FUSE_RELU_BIAS>
__global__ __launch_bounds__(256)
void sgemm_kernel(const float* __restrict__ A, const float* __restrict__ B,
                  const float* __restrict__ bias, float* __restrict__ C,
                  int M, int N, int K) {
    __shared__ float As[BK][BM];   // transposed A tile
    __shared__ float Bs[BK][BN];

    constexpr int TX = BN / TN;               // threads along n
    static_assert((BM / TM) * TX == 256, "thread count");
    constexpr int KQ = BK / 4;                // float4 per A tile row
    constexpr int AQ = BM * BK / 4;           // float4 in A tile
    constexpr int NQ = BN / 4;
    constexpr int BQ = BK * BN / 4;           // float4 in B tile

    const int tid = threadIdx.x;
    const int m0 = blockIdx.y * BM;
    const int n0 = blockIdx.x * BN;
    const int tx = tid % TX;
    const int ty = tid / TX;

    float acc[TM][TN];
#pragma unroll
    for (int i = 0; i < TM; i++)
#pragma unroll
        for (int j = 0; j < TN; j++) acc[i][j] = 0.0f;

    for (int kt = 0; kt < K; kt += BK) {
        // --- load A tile (transposed into As[k][m]) ---
#pragma unroll
        for (int i = tid; i < AQ; i += 256) {
            int ml = i / KQ;
            int kq = i % KQ;
            int gm = m0 + ml;
            float4 v = make_float4(0.f, 0.f, 0.f, 0.f);
            if (gm < M) {
                v = *(const float4*)(A + (size_t)gm * K + kt + kq * 4);
                if (FUSE_RELU_BIAS) {
                    float4 bb = *(const float4*)(bias + kt + kq * 4);
                    v.x = fmaxf(v.x + bb.x, 0.f);
                    v.y = fmaxf(v.y + bb.y, 0.f);
                    v.z = fmaxf(v.z + bb.z, 0.f);
                    v.w = fmaxf(v.w + bb.w, 0.f);
                }
            }
            As[kq * 4 + 0][ml] = v.x;
            As[kq * 4 + 1][ml] = v.y;
            As[kq * 4 + 2][ml] = v.z;
            As[kq * 4 + 3][ml] = v.w;
        }
        // --- load B tile ---
#pragma unroll
        for (int i = tid; i < BQ; i += 256) {
            int kl = i / NQ;
            int nq = i % NQ;
            float4 v = *(const float4*)(B + (size_t)(kt + kl) * N + n0 + nq * 4);
            *(float4*)(&Bs[kl][nq * 4]) = v;
        }
        __syncthreads();

#pragma unroll
        for (int k = 0; k < BK; k++) {
            float a[TM], b[TN];
#pragma unroll
            for (int i = 0; i < TM; i++) a[i] = As[k][ty * TM + i];
#pragma unroll
            for (int j = 0; j < TN; j++) b[j] = Bs[k][tx * TN + j];
#pragma unroll
            for (int i = 0; i < TM; i++)
#pragma unroll
                for (int j = 0; j < TN; j++)
                    acc[i][j] = fmaf(a[i], b[j], acc[i][j]);
        }
        __syncthreads();
    }

    // --- store ---
#pragma unroll
    for (int i = 0; i < TM; i++) {
        int gm = m0 + ty * TM + i;
        if (gm < M) {
#pragma unroll
            for (int j = 0; j < TN; j += 4) {
                float4 v = make_float4(acc[i][j], acc[i][j + 1],
                                       acc[i][j + 2], acc[i][j + 3]);
                *(float4*)(C + (size_t)gm * N + n0 + tx * TN + j) = v;
            }
        }
    }
}

// ---------------------------------------------------------------------------
// Aggregation init: self-loop term  agg[i] = h[i] * dinv[i]^2
// ---------------------------------------------------------------------------
template <int D>
__global__ void agg_init_kernel(const float* __restrict__ h, float* __restrict__ agg) {
    int q = blockIdx.x * blockDim.x + threadIdx.x;   // one float4 each
    if (q >= NN * (D / 4)) return;
    int node = q / (D / 4);
    float w = g_dinv[node];
    w = w * w;
    float4 v = ((const float4*)h)[q];
    v.x *= w; v.y *= w; v.z *= w; v.w *= w;
    ((float4*)agg)[q] = v;
}

// ---------------------------------------------------------------------------
// Edge scatter, layer 1: warp per edge (32 lanes x float4 = 128 floats)
// ---------------------------------------------------------------------------
__global__ void scatter1_kernel(const void* __restrict__ ei, int E) {
    int warp = (blockIdx.x * blockDim.x + threadIdx.x) >> 5;
    int lane = threadIdx.x & 31;
    if (warp >= E) return;
    int s, d;
    load_edge(ei, warp, E, s, d);
    float w = g_dinv[s] * g_dinv[d];
    float4 v = ((const float4*)(g_h1 + (size_t)s * D1))[lane];
    float* dst = g_a1 + (size_t)d * D1 + lane * 4;
    asm volatile("red.global.add.v4.f32 [%0], {%1, %2, %3, %4};"
                 :: "l"(dst), "f"(v.x * w), "f"(v.y * w),
                    "f"(v.z * w), "f"(v.w * w)
                 : "memory");
}

// ---------------------------------------------------------------------------
// Edge scatter, layer 2: 16 lanes per edge (16 x float4 = 64 floats)
// ---------------------------------------------------------------------------
__global__ void scatter2_kernel(const void* __restrict__ ei, int E,
                                float* __restrict__ out) {
    int idx = blockIdx.x * blockDim.x + threadIdx.x;
    int e = idx >> 4;
    int q = idx & 15;
    if (e >= E) return;
    int s, d;
    load_edge(ei, e, E, s, d);
    float w = g_dinv[s] * g_dinv[d];
    float4 v = ((const float4*)(g_h2 + (size_t)s * D2))[q];
    float* dst = out + (size_t)d * D2 + q * 4;
    asm volatile("red.global.add.v4.f32 [%0], {%1, %2, %3, %4};"
                 :: "l"(dst), "f"(v.x * w), "f"(v.y * w),
                    "f"(v.z * w), "f"(v.w * w)
                 : "memory");
}

// ---------------------------------------------------------------------------
// In-place: out[n][:] = (out[n][:] + b2) - logsumexp(out[n][:] + b2)
// Warp per node (2 values per lane).
// ---------------------------------------------------------------------------
__global__ void log_softmax_kernel(float* __restrict__ out,
                                   const float* __restrict__ b2) {
    int node = (blockIdx.x * blockDim.x + threadIdx.x) >> 5;
    int lane = threadIdx.x & 31;
    if (node >= NN) return;
    float* row = out + (size_t)node * D2;
    float v0 = row[lane] + b2[lane];
    float v1 = row[lane + 32] + b2[lane + 32];
    float m = fmaxf(v0, v1);
#pragma unroll
    for (int o = 16; o; o >>= 1) m = fmaxf(m, __shfl_xor_sync(0xffffffffu, m, o));
    float s = expf(v0 - m) + expf(v1 - m);
#pragma unroll
    for (int o = 16; o; o >>= 1) s += __shfl_xor_sync(0xffffffffu, s, o);
    float ls = m + logf(s);
    row[lane] = v0 - ls;
    row[lane + 32] = v1 - ls;
}

// ===========================================================================
// Launch
// ===========================================================================
extern "C" void kernel_launch(void* const* d_in, const int* in_sizes, int n_in,
                              void* d_out, int out_size) {
    const float* x  = (const float*)d_in[0];
    const void*  ei = d_in[1];
    const float* W1 = (const float*)d_in[2];
    const float* b1 = (const float*)d_in[3];
    const float* W2 = (const float*)d_in[4];
    const float* b2 = (const float*)d_in[5];
    float* out = (float*)d_out;

    const int E = in_sizes[1] / 2;   // element count of edge_index / 2

    float* h1 = nullptr; float* a1 = nullptr; float* h2 = nullptr;
    cudaGetSymbolAddress((void**)&h1, g_h1);
    cudaGetSymbolAddress((void**)&a1, g_a1);
    cudaGetSymbolAddress((void**)&h2, g_h2);

    // 0) edge dtype detection
    detect_kernel<<<1, 1024>>>((const int*)ei);

    // 1) degrees + dinv
    deg_init_kernel<<<(NN + 255) / 256, 256>>>();
    deg_scatter_kernel<<<(E + 255) / 256, 256>>>(ei, E);
    deg_inv_kernel<<<(NN + 255) / 256, 256>>>();

    // 2) h1 = x @ W1   (M=NN, N=128, K=128)
    {
        dim3 grid(D1 / 128, (NN + 127) / 128);
        sgemm_kernel<128, 128, 8, 8, 8, false><<<grid, 256>>>(x, W1, nullptr, h1,
                                                              NN, D1, D1);
    }

    // 3) a1 = self-loop init, then edge scatter
    agg_init_kernel<D1><<<(NN * (D1 / 4) + 255) / 256, 256>>>(h1, a1);
    scatter1_kernel<<<(E + 7) / 8, 256>>>(ei, E);   // warp per edge

    // 4) h2 = relu(a1 + b1) @ W2   (M=NN, N=64, K=128)
    {
        dim3 grid(D2 / 64, (NN + 127) / 128);
        sgemm_kernel<128, 64, 8, 8, 4, true><<<grid, 256>>>(a1, W2, b1, h2,
                                                            NN, D2, D1);
    }

    // 5) out = self-loop init, then edge scatter
    agg_init_kernel<D2><<<(NN * (D2 / 4) + 255) / 256, 256>>>(h2, out);
    scatter2_kernel<<<(E * 16 + 255) / 256, 256>>>(ei, E, out);

    // 6) log_softmax(out + b2) in place
    log_softmax_kernel<<<(NN * 32 + 255) / 256, 256>>>(out, b2);
}

// round 4
// speedup vs baseline: 2.2957x; 2.2957x over previous
#include <cuda_runtime.h>
#include <cstdint>
#include <cstddef>

// ============================================================================
// GCN 2-layer, CSR-rebuilt-per-call version.
//   N=100000 nodes, E=1.6M random edges + self loops, 128 -> 128 -> 64.
// Pipeline:
//   1) histogram deg by dst (also feeds dinv = rsqrt(1+cnt))
//   2) exclusive scan -> CSR offsets
//   3) fill CSR: per edge store {src, w = dinv[s]*dinv[d]}
//   4) h1 = x @ W1                       (f32x2 packed SGEMM)
//   5) a1[d] = h1[d]*dinv[d]^2 + sum_e w_e * h1[src_e]    (CSR gather, no atomics)
//   6) h2 = relu(a1 + b1) @ W2           (fused bias+relu in A load)
//   7) out[d] = h2[d]*dinv[d]^2 + sum_e w_e * h2[src_e]
//   8) out = log_softmax(out + b2)
// ============================================================================

#define NN    100000
#define D1    128
#define D2    64
#define EMAX  1664000
#define SCAN_B 1024
#define NBLK  ((NN + SCAN_B - 1) / SCAN_B)   // 98

typedef unsigned long long u64;

// Scratch (__device__ globals: allocation-free rule)
__device__ float g_dinv[NN];
__device__ int   g_cnt[NN];          // per-dst edge count (histogram)
__device__ int   g_off[NN];          // CSR start offsets
__device__ int   g_cur[NN];          // fill cursors
__device__ int   g_bsum[128];        // scan block sums
__device__ int2  g_edges[EMAX];      // CSR payload: {src, __float_as_int(w)}
__device__ float g_h1[(size_t)NN * D1];
__device__ float g_a1[(size_t)NN * D1];
__device__ float g_h2[(size_t)NN * D2];
__device__ int   g_is64;

// ---------------------------------------------------------------------------
// f32x2 packed-math helpers (sm_100+)
// ---------------------------------------------------------------------------
__device__ __forceinline__ u64 pack2(float lo, float hi) {
    u64 r;
    asm("mov.b64 %0, {%1, %2};" : "=l"(r) : "f"(lo), "f"(hi));
    return r;
}
__device__ __forceinline__ void ffma2(u64& d, u64 a, u64 b) {
    asm("fma.rn.f32x2 %0, %1, %2, %0;" : "+l"(d) : "l"(a), "l"(b));
}
__device__ __forceinline__ float2 unpack2(u64 v) {
    float2 f;
    asm("mov.b64 {%0, %1}, %2;" : "=f"(f.x), "=f"(f.y) : "l"(v));
    return f;
}

// ---------------------------------------------------------------------------
// Edge dtype detection: int64 nonneg values < 2^31 have all-zero high words.
// 1024 consecutive zero odd-words from random int32 node ids: impossible.
// ---------------------------------------------------------------------------
__global__ void detect_kernel(const int* __restrict__ e32) {
    int t = threadIdx.x;
    int nz = (e32[2 * t + 1] != 0) ? 1 : 0;
    int any = __syncthreads_or(nz);
    if (t == 0) g_is64 = (any == 0) ? 1 : 0;
}

__device__ __forceinline__ void load_edge(const void* __restrict__ ei, int e,
                                          int E, int& s, int& d) {
    if (g_is64) {
        const long long* p = (const long long*)ei;
        s = (int)p[e];
        d = (int)p[E + e];
    } else {
        const int* p = (const int*)ei;
        s = p[e];
        d = p[E + e];
    }
}

// ---------------------------------------------------------------------------
// CSR construction
// ---------------------------------------------------------------------------
__global__ void zero_cnt_kernel() {
    int i = blockIdx.x * blockDim.x + threadIdx.x;
    if (i < NN) g_cnt[i] = 0;
}

__global__ void hist_kernel(const void* __restrict__ ei, int E) {
    int e = blockIdx.x * blockDim.x + threadIdx.x;
    if (e >= E) return;
    int s, d;
    load_edge(ei, e, E, s, d);
    atomicAdd(&g_cnt[d], 1);
}

__global__ void dinv_kernel() {
    int i = blockIdx.x * blockDim.x + threadIdx.x;
    if (i < NN) g_dinv[i] = rsqrtf((float)(1 + g_cnt[i]));  // +1 self loop
}

// Per-block exclusive scan over g_cnt (1024 elems / block)
__global__ void scan1_kernel() {
    __shared__ int sh[SCAN_B];
    int t = threadIdx.x;
    int i = blockIdx.x * SCAN_B + t;
    int v = (i < NN) ? g_cnt[i] : 0;
    sh[t] = v;
    __syncthreads();
#pragma unroll
    for (int o = 1; o < SCAN_B; o <<= 1) {
        int x = (t >= o) ? sh[t - o] : 0;
        __syncthreads();
        sh[t] += x;
        __syncthreads();
    }
    if (i < NN) g_off[i] = sh[t] - v;           // exclusive
    if (t == SCAN_B - 1) g_bsum[blockIdx.x] = sh[t];
}

// Scan of the (<=128) block sums, single block
__global__ void scan2_kernel(int nb) {
    __shared__ int sh[128];
    int t = threadIdx.x;
    int v = (t < nb) ? g_bsum[t] : 0;
    sh[t] = v;
    __syncthreads();
#pragma unroll
    for (int o = 1; o < 128; o <<= 1) {
        int x = (t >= o) ? sh[t - o] : 0;
        __syncthreads();
        sh[t] += x;
        __syncthreads();
    }
    if (t < nb) g_bsum[t] = sh[t] - v;          // exclusive
}

__global__ void scan3_kernel() {
    int i = blockIdx.x * blockDim.x + threadIdx.x;
    if (i >= NN) return;
    int o = g_off[i] + g_bsum[i >> 10];
    g_off[i] = o;
    g_cur[i] = o;
}

__global__ void fill_kernel(const void* __restrict__ ei, int E) {
    int e = blockIdx.x * blockDim.x + threadIdx.x;
    if (e >= E) return;
    int s, d;
    load_edge(ei, e, E, s, d);
    float w = g_dinv[s] * g_dinv[d];
    int pos = atomicAdd(&g_cur[d], 1);
    g_edges[pos] = make_int2(s, __float_as_int(w));
}

// ---------------------------------------------------------------------------
// Register-tiled SGEMM, packed f32x2 inner product.
// C[M,N] = A[M,K] @ B[K,N]; optionally A := relu(A + bias[k]) on load.
// ---------------------------------------------------------------------------
template <int BM, int BN, int BK, int TM, int TN, bool FUSE_RELU_BIAS>
__global__ __launch_bounds__(256)
void sgemm_kernel(const float* __restrict__ A, const float* __restrict__ B,
                  const float* __restrict__ bias, float* __restrict__ C,
                  int M, int N, int K) {
    __shared__ float As[BK][BM];   // transposed A tile
    __shared__ float Bs[BK][BN];

    constexpr int TX = BN / TN;
    static_assert((BM / TM) * TX == 256, "thread count");
    static_assert(TN % 4 == 0 && TM % 4 == 0, "vec");
    constexpr int KQ = BK / 4;
    constexpr int AQ = BM * BK / 4;
    constexpr int NQ = BN / 4;
    constexpr int BQ = BK * BN / 4;
    constexpr int TNH = TN / 2;

    const int tid = threadIdx.x;
    const int m0 = blockIdx.y * BM;
    const int n0 = blockIdx.x * BN;
    const int tx = tid % TX;
    const int ty = tid / TX;

    u64 acc[TM][TNH];
#pragma unroll
    for (int i = 0; i < TM; i++)
#pragma unroll
        for (int j = 0; j < TNH; j++) acc[i][j] = 0ull;

    for (int kt = 0; kt < K; kt += BK) {
#pragma unroll
        for (int i = tid; i < AQ; i += 256) {
            int ml = i / KQ;
            int kq = i % KQ;
            int gm = m0 + ml;
            float4 v = make_float4(0.f, 0.f, 0.f, 0.f);
            if (gm < M) {
                v = *(const float4*)(A + (size_t)gm * K + kt + kq * 4);
                if (FUSE_RELU_BIAS) {
                    float4 bb = *(const float4*)(bias + kt + kq * 4);
                    v.x = fmaxf(v.x + bb.x, 0.f);
                    v.y = fmaxf(v.y + bb.y, 0.f);
                    v.z = fmaxf(v.z + bb.z, 0.f);
                    v.w = fmaxf(v.w + bb.w, 0.f);
                }
            }
            As[kq * 4 + 0][ml] = v.x;
            As[kq * 4 + 1][ml] = v.y;
            As[kq * 4 + 2][ml] = v.z;
            As[kq * 4 + 3][ml] = v.w;
        }
#pragma unroll
        for (int i = tid; i < BQ; i += 256) {
            int kl = i / NQ;
            int nq = i % NQ;
            *(float4*)(&Bs[kl][nq * 4]) =
                *(const float4*)(B + (size_t)(kt + kl) * N + n0 + nq * 4);
        }
        __syncthreads();

#pragma unroll
        for (int k = 0; k < BK; k++) {
            float a[TM];
#pragma unroll
            for (int i = 0; i < TM; i += 4)
                *(float4*)&a[i] = *(const float4*)&As[k][ty * TM + i];
            u64 br[TNH];
#pragma unroll
            for (int j = 0; j < TNH; j++)
                br[j] = *(const u64*)&Bs[k][tx * TN + 2 * j];
#pragma unroll
            for (int i = 0; i < TM; i++) {
                u64 a2 = pack2(a[i], a[i]);
#pragma unroll
                for (int j = 0; j < TNH; j++)
                    ffma2(acc[i][j], a2, br[j]);
            }
        }
        __syncthreads();
    }

#pragma unroll
    for (int i = 0; i < TM; i++) {
        int gm = m0 + ty * TM + i;
        if (gm < M) {
#pragma unroll
            for (int j = 0; j < TNH; j += 2) {
                float2 f0 = unpack2(acc[i][j]);
                float2 f1 = unpack2(acc[i][j + 1]);
                float4 v = make_float4(f0.x, f0.y, f1.x, f1.y);
                *(float4*)(C + (size_t)gm * N + n0 + tx * TN + 2 * j) = v;
            }
        }
    }
}

// ---------------------------------------------------------------------------
// CSR aggregation, layer 1: warp per dst node, lane owns a float4 (128 dims).
// acc = h[node]*dinv^2 + sum_e w_e * h[src_e]. No atomics, streaming store.
// Edge metadata batched: lane L loads edge (base+L), broadcast via shfl.
// ---------------------------------------------------------------------------
__global__ void agg1_kernel(const float* __restrict__ h, float* __restrict__ a) {
    int node = (blockIdx.x * blockDim.x + threadIdx.x) >> 5;
    int lane = threadIdx.x & 31;
    if (node >= NN) return;
    int beg = g_off[node];
    int cnt = g_cnt[node];
    float di = g_dinv[node];
    float w0 = di * di;

    float4 acc = ((const float4*)(h + (size_t)node * D1))[lane];
    acc.x *= w0; acc.y *= w0; acc.z *= w0; acc.w *= w0;
    float4 acc2 = make_float4(0.f, 0.f, 0.f, 0.f);

    for (int base = 0; base < cnt; base += 32) {
        int rem = cnt - base;
        int m = rem < 32 ? rem : 32;
        int2 e = make_int2(0, 0);
        if (lane < m) e = g_edges[beg + base + lane];
        int j = 0;
        for (; j + 1 < m; j += 2) {
            int   s0 = __shfl_sync(0xffffffffu, e.x, j);
            float w_0 = __int_as_float(__shfl_sync(0xffffffffu, e.y, j));
            int   s1 = __shfl_sync(0xffffffffu, e.x, j + 1);
            float w_1 = __int_as_float(__shfl_sync(0xffffffffu, e.y, j + 1));
            float4 v0 = ((const float4*)(h + (size_t)s0 * D1))[lane];
            float4 v1 = ((const float4*)(h + (size_t)s1 * D1))[lane];
            acc.x  = fmaf(v0.x, w_0, acc.x);
            acc.y  = fmaf(v0.y, w_0, acc.y);
            acc.z  = fmaf(v0.z, w_0, acc.z);
            acc.w  = fmaf(v0.w, w_0, acc.w);
            acc2.x = fmaf(v1.x, w_1, acc2.x);
            acc2.y = fmaf(v1.y, w_1, acc2.y);
            acc2.z = fmaf(v1.z, w_1, acc2.z);
            acc2.w = fmaf(v1.w, w_1, acc2.w);
        }
        if (j < m) {
            int   s0 = __shfl_sync(0xffffffffu, e.x, j);
            float w_0 = __int_as_float(__shfl_sync(0xffffffffu, e.y, j));
            float4 v0 = ((const float4*)(h + (size_t)s0 * D1))[lane];
            acc.x = fmaf(v0.x, w_0, acc.x);
            acc.y = fmaf(v0.y, w_0, acc.y);
            acc.z = fmaf(v0.z, w_0, acc.z);
            acc.w = fmaf(v0.w, w_0, acc.w);
        }
    }
    acc.x += acc2.x; acc.y += acc2.y; acc.z += acc2.z; acc.w += acc2.w;
    ((float4*)(a + (size_t)node * D1))[lane] = acc;
}

// ---------------------------------------------------------------------------
// CSR aggregation, layer 2: warp per dst node, lane owns a float2 (64 dims).
// ---------------------------------------------------------------------------
__global__ void agg2_kernel(const float* __restrict__ h, float* __restrict__ a) {
    int node = (blockIdx.x * blockDim.x + threadIdx.x) >> 5;
    int lane = threadIdx.x & 31;
    if (node >= NN) return;
    int beg = g_off[node];
    int cnt = g_cnt[node];
    float di = g_dinv[node];
    float w0 = di * di;

    float2 acc = ((const float2*)(h + (size_t)node * D2))[lane];
    acc.x *= w0; acc.y *= w0;
    float2 acc2 = make_float2(0.f, 0.f);

    for (int base = 0; base < cnt; base += 32) {
        int rem = cnt - base;
        int m = rem < 32 ? rem : 32;
        int2 e = make_int2(0, 0);
        if (lane < m) e = g_edges[beg + base + lane];
        int j = 0;
        for (; j + 1 < m; j += 2) {
            int   s0 = __shfl_sync(0xffffffffu, e.x, j);
            float w_0 = __int_as_float(__shfl_sync(0xffffffffu, e.y, j));
            int   s1 = __shfl_sync(0xffffffffu, e.x, j + 1);
            float w_1 = __int_as_float(__shfl_sync(0xffffffffu, e.y, j + 1));
            float2 v0 = ((const float2*)(h + (size_t)s0 * D2))[lane];
            float2 v1 = ((const float2*)(h + (size_t)s1 * D2))[lane];
            acc.x  = fmaf(v0.x, w_0, acc.x);
            acc.y  = fmaf(v0.y, w_0, acc.y);
            acc2.x = fmaf(v1.x, w_1, acc2.x);
            acc2.y = fmaf(v1.y, w_1, acc2.y);
        }
        if (j < m) {
            int   s0 = __shfl_sync(0xffffffffu, e.x, j);
            float w_0 = __int_as_float(__shfl_sync(0xffffffffu, e.y, j));
            float2 v0 = ((const float2*)(h + (size_t)s0 * D2))[lane];
            acc.x = fmaf(v0.x, w_0, acc.x);
            acc.y = fmaf(v0.y, w_0, acc.y);
        }
    }
    acc.x += acc2.x; acc.y += acc2.y;
    ((float2*)(a + (size_t)node * D2))[lane] = acc;
}

// ---------------------------------------------------------------------------
// In place: out[n][:] = (out[n][:] + b2) - logsumexp(...). Warp per node.
// ---------------------------------------------------------------------------
__global__ void log_softmax_kernel(float* __restrict__ out,
                                   const float* __restrict__ b2) {
    int node = (blockIdx.x * blockDim.x + threadIdx.x) >> 5;
    int lane = threadIdx.x & 31;
    if (node >= NN) return;
    float* row = out + (size_t)node * D2;
    float v0 = row[lane] + b2[lane];
    float v1 = row[lane + 32] + b2[lane + 32];
    float m = fmaxf(v0, v1);
#pragma unroll
    for (int o = 16; o; o >>= 1) m = fmaxf(m, __shfl_xor_sync(0xffffffffu, m, o));
    float s = expf(v0 - m) + expf(v1 - m);
#pragma unroll
    for (int o = 16; o; o >>= 1) s += __shfl_xor_sync(0xffffffffu, s, o);
    float ls = m + logf(s);
    row[lane] = v0 - ls;
    row[lane + 32] = v1 - ls;
}

// ===========================================================================
// Launch
// ===========================================================================
extern "C" void kernel_launch(void* const* d_in, const int* in_sizes, int n_in,
                              void* d_out, int out_size) {
    const float* x  = (const float*)d_in[0];
    const void*  ei = d_in[1];
    const float* W1 = (const float*)d_in[2];
    const float* b1 = (const float*)d_in[3];
    const float* W2 = (const float*)d_in[4];
    const float* b2 = (const float*)d_in[5];
    float* out = (float*)d_out;

    const int E = in_sizes[1] / 2;

    float* h1 = nullptr; float* a1 = nullptr; float* h2 = nullptr;
    cudaGetSymbolAddress((void**)&h1, g_h1);
    cudaGetSymbolAddress((void**)&a1, g_a1);
    cudaGetSymbolAddress((void**)&h2, g_h2);

    // 0) dtype
    detect_kernel<<<1, 1024>>>((const int*)ei);

    // 1) CSR build + dinv
    zero_cnt_kernel<<<(NN + 255) / 256, 256>>>();
    hist_kernel<<<(E + 255) / 256, 256>>>(ei, E);
    dinv_kernel<<<(NN + 255) / 256, 256>>>();
    scan1_kernel<<<NBLK, SCAN_B>>>();
    scan2_kernel<<<1, 128>>>(NBLK);
    scan3_kernel<<<(NN + 255) / 256, 256>>>();
    fill_kernel<<<(E + 255) / 256, 256>>>(ei, E);

    // 2) h1 = x @ W1   (M=NN, N=128, K=128)
    {
        dim3 grid(D1 / 128, (NN + 127) / 128);
        sgemm_kernel<128, 128, 8, 8, 8, false><<<grid, 256>>>(x, W1, nullptr, h1,
                                                              NN, D1, D1);
    }

    // 3) a1 = CSR aggregate of h1 (self loop folded in)
    agg1_kernel<<<(NN * 32 + 255) / 256, 256>>>(h1, a1);

    // 4) h2 = relu(a1 + b1) @ W2   (M=NN, N=64, K=128)
    {
        dim3 grid(D2 / 64, (NN + 127) / 128);
        sgemm_kernel<128, 64, 8, 8, 4, true><<<grid, 256>>>(a1, W2, b1, h2,
                                                            NN, D2, D1);
    }

    // 5) out = CSR aggregate of h2
    agg2_kernel<<<(NN * 32 + 255) / 256, 256>>>(h2, out);

    // 6) log_softmax(out + b2)
    log_softmax_kernel<<<(NN * 32 + 255) / 256, 256>>>(out, b2);
}

// round 5
// speedup vs baseline: 2.7026x; 1.1772x over previous
#include <cuda_runtime.h>
#include <cstdint>
#include <cstddef>

// ============================================================================
// GCN 2-layer, CSR per-call, stream-overlapped.
//   N=100000, E=1.6M (+self loops), 128 -> 128 -> 64.
//   side stream: CSR build (hist -> scan -> fill) overlapped with GEMM1.
//   main stream: h1 = x@W1 ; a1 = csr_agg(h1) ; h2 = relu(a1+b1)@W2 ;
//                out = log_softmax(csr_agg(h2) + b2)   (agg+softmax fused)
// ============================================================================

#define NN    100000
#define D1    128
#define D2    64
#define EMAX  1664000
#define SCAN_B 1024
#define NBLK  ((NN + SCAN_B - 1) / SCAN_B)   // 98

typedef unsigned long long u64;

__device__ float g_dinv[NN];
__device__ int   g_cnt[NN];
__device__ int   g_off[NN];
__device__ int   g_cur[NN];
__device__ int   g_bsum[128];
__device__ int2  g_edges[EMAX];              // {src, __float_as_int(w)}
__device__ float g_h1[(size_t)NN * D1];
__device__ float g_a1[(size_t)NN * D1];
__device__ float g_h2[(size_t)NN * D2];
__device__ int   g_is64;

// ---------------------------------------------------------------------------
// f32x2 packed math (sm_100+)
// ---------------------------------------------------------------------------
__device__ __forceinline__ u64 pack2(float lo, float hi) {
    u64 r;
    asm("mov.b64 %0, {%1, %2};" : "=l"(r) : "f"(lo), "f"(hi));
    return r;
}
__device__ __forceinline__ void ffma2(u64& d, u64 a, u64 b) {
    asm("fma.rn.f32x2 %0, %1, %2, %0;" : "+l"(d) : "l"(a), "l"(b));
}
__device__ __forceinline__ float2 unpack2(u64 v) {
    float2 f;
    asm("mov.b64 {%0, %1}, %2;" : "=f"(f.x), "=f"(f.y) : "l"(v));
    return f;
}

// ---------------------------------------------------------------------------
// Edge dtype detection (int64 high words of nonneg < 2^31 are all zero)
// ---------------------------------------------------------------------------
__global__ void detect_kernel(const int* __restrict__ e32) {
    int t = threadIdx.x;
    int nz = (e32[2 * t + 1] != 0) ? 1 : 0;
    int any = __syncthreads_or(nz);
    if (t == 0) g_is64 = (any == 0) ? 1 : 0;
}

__device__ __forceinline__ void load_edge(const void* __restrict__ ei, int e,
                                          int E, int& s, int& d) {
    if (g_is64) {
        const long long* p = (const long long*)ei;
        s = (int)p[e];
        d = (int)p[E + e];
    } else {
        const int* p = (const int*)ei;
        s = p[e];
        d = p[E + e];
    }
}

// ---------------------------------------------------------------------------
// CSR construction
// ---------------------------------------------------------------------------
__global__ void zero_cnt_kernel() {
    int i = blockIdx.x * blockDim.x + threadIdx.x;
    if (i < NN) g_cnt[i] = 0;
}

__global__ void hist_kernel(const void* __restrict__ ei, int E) {
    int e = blockIdx.x * blockDim.x + threadIdx.x;
    if (e >= E) return;
    int s, d;
    load_edge(ei, e, E, s, d);
    atomicAdd(&g_cnt[d], 1);
}

__global__ void dinv_kernel() {
    int i = blockIdx.x * blockDim.x + threadIdx.x;
    if (i < NN) g_dinv[i] = rsqrtf((float)(1 + g_cnt[i]));
}

__global__ void scan1_kernel() {
    __shared__ int sh[SCAN_B];
    int t = threadIdx.x;
    int i = blockIdx.x * SCAN_B + t;
    int v = (i < NN) ? g_cnt[i] : 0;
    sh[t] = v;
    __syncthreads();
#pragma unroll
    for (int o = 1; o < SCAN_B; o <<= 1) {
        int x = (t >= o) ? sh[t - o] : 0;
        __syncthreads();
        sh[t] += x;
        __syncthreads();
    }
    if (i < NN) g_off[i] = sh[t] - v;
    if (t == SCAN_B - 1) g_bsum[blockIdx.x] = sh[t];
}

__global__ void scan2_kernel(int nb) {
    __shared__ int sh[128];
    int t = threadIdx.x;
    int v = (t < nb) ? g_bsum[t] : 0;
    sh[t] = v;
    __syncthreads();
#pragma unroll
    for (int o = 1; o < 128; o <<= 1) {
        int x = (t >= o) ? sh[t - o] : 0;
        __syncthreads();
        sh[t] += x;
        __syncthreads();
    }
    if (t < nb) g_bsum[t] = sh[t] - v;
}

__global__ void scan3_kernel() {
    int i = blockIdx.x * blockDim.x + threadIdx.x;
    if (i >= NN) return;
    int o = g_off[i] + g_bsum[i >> 10];
    g_off[i] = o;
    g_cur[i] = o;
}

__global__ void fill_kernel(const void* __restrict__ ei, int E) {
    int e = blockIdx.x * blockDim.x + threadIdx.x;
    if (e >= E) return;
    int s, d;
    load_edge(ei, e, E, s, d);
    float w = g_dinv[s] * g_dinv[d];
    int pos = atomicAdd(&g_cur[d], 1);
    g_edges[pos] = make_int2(s, __float_as_int(w));
}

// ---------------------------------------------------------------------------
// Pipelined, double-buffered SGEMM with f32x2 inner product.
// C[M,N] = A[M,K] @ B[K,N]; optionally A := relu(A + bias[k]) on load.
// ---------------------------------------------------------------------------
template <int BM, int BN, int BK, int TM, int TN, bool FUSE_RELU_BIAS>
__global__ __launch_bounds__(256)
void sgemm_kernel(const float* __restrict__ A, const float* __restrict__ B,
                  const float* __restrict__ bias, float* __restrict__ C,
                  int M, int N, int K) {
    __shared__ float As[2][BK][BM + 4];   // +4 pad: kill STS bank conflicts
    __shared__ float Bs[2][BK][BN];

    constexpr int TX = BN / TN;
    static_assert((BM / TM) * TX == 256, "thread count");
    constexpr int KQ = BK / 4;
    constexpr int AQ = BM * BK / 4;
    constexpr int NQ = BN / 4;
    constexpr int BQ = BK * BN / 4;
    constexpr int TNH = TN / 2;
    constexpr int ALD = AQ / 256;         // float4 A loads per thread
    constexpr int BLD = BQ / 256;
    static_assert(ALD * 256 == AQ && BLD * 256 == BQ, "exact split");

    const int tid = threadIdx.x;
    const int m0 = blockIdx.y * BM;
    const int n0 = blockIdx.x * BN;
    const int tx = tid % TX;
    const int ty = tid / TX;

    float4 ar[ALD];
    float4 br[BLD];

    u64 acc[TM][TNH];
#pragma unroll
    for (int i = 0; i < TM; i++)
#pragma unroll
        for (int j = 0; j < TNH; j++) acc[i][j] = 0ull;

    // ---- tile loaders (global -> regs), storers (regs -> smem) ----
    auto load_tiles = [&](int kt) {
#pragma unroll
        for (int u = 0; u < ALD; u++) {
            int i = tid + u * 256;
            int ml = i / KQ;
            int kq = i % KQ;
            int gm = m0 + ml;
            float4 v = make_float4(0.f, 0.f, 0.f, 0.f);
            if (gm < M) {
                v = *(const float4*)(A + (size_t)gm * K + kt + kq * 4);
                if (FUSE_RELU_BIAS) {
                    float4 bb = *(const float4*)(bias + kt + kq * 4);
                    v.x = fmaxf(v.x + bb.x, 0.f);
                    v.y = fmaxf(v.y + bb.y, 0.f);
                    v.z = fmaxf(v.z + bb.z, 0.f);
                    v.w = fmaxf(v.w + bb.w, 0.f);
                }
            }
            ar[u] = v;
        }
#pragma unroll
        for (int u = 0; u < BLD; u++) {
            int i = tid + u * 256;
            int kl = i / NQ;
            int nq = i % NQ;
            br[u] = *(const float4*)(B + (size_t)(kt + kl) * N + n0 + nq * 4);
        }
    };
    auto store_tiles = [&](int b) {
#pragma unroll
        for (int u = 0; u < ALD; u++) {
            int i = tid + u * 256;
            int ml = i / KQ;
            int kq = i % KQ;
            As[b][kq * 4 + 0][ml] = ar[u].x;
            As[b][kq * 4 + 1][ml] = ar[u].y;
            As[b][kq * 4 + 2][ml] = ar[u].z;
            As[b][kq * 4 + 3][ml] = ar[u].w;
        }
#pragma unroll
        for (int u = 0; u < BLD; u++) {
            int i = tid + u * 256;
            int kl = i / NQ;
            int nq = i % NQ;
            *(float4*)(&Bs[b][kl][nq * 4]) = br[u];
        }
    };

    // ---- pipeline: prologue ----
    load_tiles(0);
    store_tiles(0);
    __syncthreads();

    int buf = 0;
    for (int kt = 0; kt < K; kt += BK) {
        const int ktn = kt + BK;
        const bool has_next = ktn < K;
        if (has_next) load_tiles(ktn);      // global loads overlap compute

#pragma unroll
        for (int k = 0; k < BK; k++) {
            float a[TM];
#pragma unroll
            for (int i = 0; i < TM; i += 4)
                *(float4*)&a[i] = *(const float4*)&As[buf][k][ty * TM + i];
            u64 b2r[TNH];
#pragma unroll
            for (int j = 0; j < TNH; j += 2) {
                float4 v = *(const float4*)&Bs[buf][k][tx * TN + 2 * j];
                b2r[j] = pack2(v.x, v.y);
                b2r[j + 1] = pack2(v.z, v.w);
            }
#pragma unroll
            for (int i = 0; i < TM; i++) {
                u64 a2 = pack2(a[i], a[i]);
#pragma unroll
                for (int j = 0; j < TNH; j++)
                    ffma2(acc[i][j], a2, b2r[j]);
            }
        }

        if (has_next) {
            store_tiles(buf ^ 1);           // other buffer: no race w/ compute
            __syncthreads();
            buf ^= 1;
        }
    }

    // ---- store C ----
#pragma unroll
    for (int i = 0; i < TM; i++) {
        int gm = m0 + ty * TM + i;
        if (gm < M) {
#pragma unroll
            for (int j = 0; j < TNH; j += 2) {
                float2 f0 = unpack2(acc[i][j]);
                float2 f1 = unpack2(acc[i][j + 1]);
                float4 v = make_float4(f0.x, f0.y, f1.x, f1.y);
                *(float4*)(C + (size_t)gm * N + n0 + tx * TN + 2 * j) = v;
            }
        }
    }
}

// ---------------------------------------------------------------------------
// CSR aggregation, layer 1: warp per dst node, lane owns a float4 (128 dims).
// ---------------------------------------------------------------------------
__global__ void agg1_kernel(const float* __restrict__ h, float* __restrict__ a) {
    int node = (blockIdx.x * blockDim.x + threadIdx.x) >> 5;
    int lane = threadIdx.x & 31;
    if (node >= NN) return;
    int beg = g_off[node];
    int cnt = g_cnt[node];
    float di = g_dinv[node];
    float w0 = di * di;

    float4 acc = ((const float4*)(h + (size_t)node * D1))[lane];
    acc.x *= w0; acc.y *= w0; acc.z *= w0; acc.w *= w0;
    float4 acc2 = make_float4(0.f, 0.f, 0.f, 0.f);

    for (int base = 0; base < cnt; base += 32) {
        int rem = cnt - base;
        int m = rem < 32 ? rem : 32;
        int2 e = make_int2(0, 0);
        if (lane < m) e = g_edges[beg + base + lane];
        int j = 0;
        for (; j + 1 < m; j += 2) {
            int   s0  = __shfl_sync(0xffffffffu, e.x, j);
            float w_0 = __int_as_float(__shfl_sync(0xffffffffu, e.y, j));
            int   s1  = __shfl_sync(0xffffffffu, e.x, j + 1);
            float w_1 = __int_as_float(__shfl_sync(0xffffffffu, e.y, j + 1));
            float4 v0 = ((const float4*)(h + (size_t)s0 * D1))[lane];
            float4 v1 = ((const float4*)(h + (size_t)s1 * D1))[lane];
            acc.x  = fmaf(v0.x, w_0, acc.x);
            acc.y  = fmaf(v0.y, w_0, acc.y);
            acc.z  = fmaf(v0.z, w_0, acc.z);
            acc.w  = fmaf(v0.w, w_0, acc.w);
            acc2.x = fmaf(v1.x, w_1, acc2.x);
            acc2.y = fmaf(v1.y, w_1, acc2.y);
            acc2.z = fmaf(v1.z, w_1, acc2.z);
            acc2.w = fmaf(v1.w, w_1, acc2.w);
        }
        if (j < m) {
            int   s0  = __shfl_sync(0xffffffffu, e.x, j);
            float w_0 = __int_as_float(__shfl_sync(0xffffffffu, e.y, j));
            float4 v0 = ((const float4*)(h + (size_t)s0 * D1))[lane];
            acc.x = fmaf(v0.x, w_0, acc.x);
            acc.y = fmaf(v0.y, w_0, acc.y);
            acc.z = fmaf(v0.z, w_0, acc.z);
            acc.w = fmaf(v0.w, w_0, acc.w);
        }
    }
    acc.x += acc2.x; acc.y += acc2.y; acc.z += acc2.z; acc.w += acc2.w;
    ((float4*)(a + (size_t)node * D1))[lane] = acc;
}

// ---------------------------------------------------------------------------
// CSR aggregation layer 2 FUSED with bias + log_softmax.
// Warp per dst node; lane owns float2 = dims (2*lane, 2*lane+1).
// ---------------------------------------------------------------------------
__global__ void agg2_softmax_kernel(const float* __restrict__ h,
                                    const float* __restrict__ b2,
                                    float* __restrict__ out) {
    int node = (blockIdx.x * blockDim.x + threadIdx.x) >> 5;
    int lane = threadIdx.x & 31;
    if (node >= NN) return;
    int beg = g_off[node];
    int cnt = g_cnt[node];
    float di = g_dinv[node];
    float w0 = di * di;

    float2 acc = ((const float2*)(h + (size_t)node * D2))[lane];
    acc.x *= w0; acc.y *= w0;
    float2 acc2 = make_float2(0.f, 0.f);

    for (int base = 0; base < cnt; base += 32) {
        int rem = cnt - base;
        int m = rem < 32 ? rem : 32;
        int2 e = make_int2(0, 0);
        if (lane < m) e = g_edges[beg + base + lane];
        int j = 0;
        for (; j + 1 < m; j += 2) {
            int   s0  = __shfl_sync(0xffffffffu, e.x, j);
            float w_0 = __int_as_float(__shfl_sync(0xffffffffu, e.y, j));
            int   s1  = __shfl_sync(0xffffffffu, e.x, j + 1);
            float w_1 = __int_as_float(__shfl_sync(0xffffffffu, e.y, j + 1));
            float2 v0 = ((const float2*)(h + (size_t)s0 * D2))[lane];
            float2 v1 = ((const float2*)(h + (size_t)s1 * D2))[lane];
            acc.x  = fmaf(v0.x, w_0, acc.x);
            acc.y  = fmaf(v0.y, w_0, acc.y);
            acc2.x = fmaf(v1.x, w_1, acc2.x);
            acc2.y = fmaf(v1.y, w_1, acc2.y);
        }
        if (j < m) {
            int   s0  = __shfl_sync(0xffffffffu, e.x, j);
            float w_0 = __int_as_float(__shfl_sync(0xffffffffu, e.y, j));
            float2 v0 = ((const float2*)(h + (size_t)s0 * D2))[lane];
            acc.x = fmaf(v0.x, w_0, acc.x);
            acc.y = fmaf(v0.y, w_0, acc.y);
        }
    }
    // bias + log_softmax in registers
    float2 bb = ((const float2*)b2)[lane];
    float v0 = acc.x + acc2.x + bb.x;
    float v1 = acc.y + acc2.y + bb.y;
    float mx = fmaxf(v0, v1);
#pragma unroll
    for (int o = 16; o; o >>= 1) mx = fmaxf(mx, __shfl_xor_sync(0xffffffffu, mx, o));
    float s = expf(v0 - mx) + expf(v1 - mx);
#pragma unroll
    for (int o = 16; o; o >>= 1) s += __shfl_xor_sync(0xffffffffu, s, o);
    float ls = mx + logf(s);
    ((float2*)(out + (size_t)node * D2))[lane] = make_float2(v0 - ls, v1 - ls);
}

// ===========================================================================
// Launch: fork-join capture — CSR chain on side stream under GEMM1.
// ===========================================================================
extern "C" void kernel_launch(void* const* d_in, const int* in_sizes, int n_in,
                              void* d_out, int out_size) {
    const float* x  = (const float*)d_in[0];
    const void*  ei = d_in[1];
    const float* W1 = (const float*)d_in[2];
    const float* b1 = (const float*)d_in[3];
    const float* W2 = (const float*)d_in[4];
    const float* b2 = (const float*)d_in[5];
    float* out = (float*)d_out;

    const int E = in_sizes[1] / 2;

    float* h1 = nullptr; float* a1 = nullptr; float* h2 = nullptr;
    cudaGetSymbolAddress((void**)&h1, g_h1);
    cudaGetSymbolAddress((void**)&a1, g_a1);
    cudaGetSymbolAddress((void**)&h2, g_h2);

    // One-time stream/event setup (resource creation, not work; happens on
    // the uncaptured correctness call first).
    static cudaStream_t side = nullptr;
    static cudaEvent_t evF = nullptr, evJ = nullptr;
    if (side == nullptr) {
        cudaStreamCreateWithFlags(&side, cudaStreamNonBlocking);
        cudaEventCreateWithFlags(&evF, cudaEventDisableTiming);
        cudaEventCreateWithFlags(&evJ, cudaEventDisableTiming);
    }

    // ---- fork: side stream builds CSR while main stream runs GEMM1 ----
    cudaEventRecord(evF, 0);
    cudaStreamWaitEvent(side, evF, 0);

    detect_kernel<<<1, 1024, 0, side>>>((const int*)ei);
    zero_cnt_kernel<<<(NN + 255) / 256, 256, 0, side>>>();
    hist_kernel<<<(E + 255) / 256, 256, 0, side>>>(ei, E);
    dinv_kernel<<<(NN + 255) / 256, 256, 0, side>>>();
    scan1_kernel<<<NBLK, SCAN_B, 0, side>>>();
    scan2_kernel<<<1, 128, 0, side>>>(NBLK);
    scan3_kernel<<<(NN + 255) / 256, 256, 0, side>>>();
    fill_kernel<<<(E + 255) / 256, 256, 0, side>>>(ei, E);
    cudaEventRecord(evJ, side);

    // main: h1 = x @ W1   (M=NN, N=128, K=128)
    {
        dim3 grid(D1 / 128, (NN + 127) / 128);
        sgemm_kernel<128, 128, 16, 8, 8, false><<<grid, 256>>>(x, W1, nullptr,
                                                               h1, NN, D1, D1);
    }

    // ---- join ----
    cudaStreamWaitEvent(0, evJ, 0);

    // a1 = CSR aggregate of h1 (self loop folded)
    agg1_kernel<<<(NN * 32 + 255) / 256, 256>>>(h1, a1);

    // h2 = relu(a1 + b1) @ W2   (M=NN, N=64, K=128)
    {
        dim3 grid(D2 / 64, (NN + 127) / 128);
        sgemm_kernel<128, 64, 16, 8, 4, true><<<grid, 256>>>(a1, W2, b1, h2,
                                                             NN, D2, D1);
    }

    // out = log_softmax(CSR aggregate of h2 + b2)  -- fused
    agg2_softmax_kernel<<<(NN * 32 + 255) / 256, 256>>>(h2, b2, out);
}